// round 4
// baseline (speedup 1.0000x reference)
#include <cuda_runtime.h>
#include <cuda_bf16.h>
#include <cstdint>

#define T 1024
#define H 1024
#define F 768
#define E 32
#define K 4

#define KC 32            // k elems per chunk
#define PITCH_B 80       // bytes per smem row -> conflict-free ldmatrix
#define ASZ (128 * PITCH_B)
#define BUF_STRIDE (4 * ASZ)
#define SMEM_TOTAL (2 * BUF_STRIDE)   /* 81920 */
#define NC1 (H / KC)     // 32
#define NC2 (F / KC)     // 24

// ---------------- scratch ----------------
__device__ float    g_topk_w[T * K];
__device__ int      g_topk_id[T * K];
__device__ int      g_count[E];
__device__ int      g_offset[E + 1];
__device__ int      g_cursor[E];
__device__ int      g_assign_token[T * K];
__device__ int      g_row_of[T * K];
__device__ uint32_t g_hs_pk[(size_t)T * H];       // packed bf16 hi|lo<<16, 4MB
__device__ uint32_t g_act_pk[(size_t)T * K * F];  // packed bf16 hi|lo<<16, ~12.6MB
__device__ float    g_y[(size_t)T * K * H];       // ~16.8MB

// ---------------- helpers ----------------
__device__ __forceinline__ uint32_t smem_u32(const void* p) {
    uint32_t a;
    asm("{ .reg .u64 t; cvta.to.shared.u64 t, %1; cvt.u32.u64 %0, t; }" : "=r"(a) : "l"(p));
    return a;
}

#define LDM4(r, addr) \
    asm volatile("ldmatrix.sync.aligned.m8n8.x4.shared.b16 {%0,%1,%2,%3}, [%4];" \
        : "=r"((r)[0]), "=r"((r)[1]), "=r"((r)[2]), "=r"((r)[3]) : "r"(addr))

#define MMA16816(d, a, b0, b1) \
    asm volatile("mma.sync.aligned.m16n8k16.row.col.f32.bf16.bf16.f32 " \
        "{%0,%1,%2,%3}, {%4,%5,%6,%7}, {%8,%9}, {%0,%1,%2,%3};" \
        : "+f"((d)[0]), "+f"((d)[1]), "+f"((d)[2]), "+f"((d)[3]) \
        : "r"((a)[0]), "r"((a)[1]), "r"((a)[2]), "r"((a)[3]), "r"(b0), "r"(b1))

// split float4 -> bf16 hi pair-packed + lo pair-packed
__device__ __forceinline__ void cvt_split4(float4 v, uint2& hi, uint2& lo) {
    uint32_t h01, h23, l01, l23;
    asm("cvt.rn.bf16x2.f32 %0, %1, %2;" : "=r"(h01) : "f"(v.y), "f"(v.x));
    asm("cvt.rn.bf16x2.f32 %0, %1, %2;" : "=r"(h23) : "f"(v.w), "f"(v.z));
    float h0 = __uint_as_float(h01 << 16), h1 = __uint_as_float(h01 & 0xFFFF0000u);
    float h2 = __uint_as_float(h23 << 16), h3 = __uint_as_float(h23 & 0xFFFF0000u);
    asm("cvt.rn.bf16x2.f32 %0, %1, %2;" : "=r"(l01) : "f"(v.y - h1), "f"(v.x - h0));
    asm("cvt.rn.bf16x2.f32 %0, %1, %2;" : "=r"(l23) : "f"(v.w - h3), "f"(v.z - h2));
    hi = make_uint2(h01, h23);
    lo = make_uint2(l01, l23);
}

// unpack 4 packed u32 -> hi uint2 / lo uint2
__device__ __forceinline__ void unpack4(uint4 p, uint2& hi, uint2& lo) {
    hi.x = __byte_perm(p.x, p.y, 0x5410);
    hi.y = __byte_perm(p.z, p.w, 0x5410);
    lo.x = __byte_perm(p.x, p.y, 0x7632);
    lo.y = __byte_perm(p.z, p.w, 0x7632);
}

__device__ __forceinline__ uint32_t pack_hl(float a) {
    __nv_bfloat16 h = __float2bfloat16(a);
    float hf = __bfloat162float(h);
    __nv_bfloat16 l = __float2bfloat16(a - hf);
    return (uint32_t)__bfloat16_as_ushort(h) | ((uint32_t)__bfloat16_as_ushort(l) << 16);
}

__device__ __forceinline__ float silu(float x) { return x / (1.f + __expf(-x)); }

// ---------------- init / hs preconvert ----------------
__global__ void init_kernel() {
    int i = threadIdx.x;
    if (i < E) g_count[i] = 0;
}

__global__ void hs_convert_kernel(const float* __restrict__ hs) {
    int i = blockIdx.x * blockDim.x + threadIdx.x;   // one float4 per thread
    float4 v = *(const float4*)(hs + (size_t)i * 4);
    uint4 p;
    p.x = pack_hl(v.x); p.y = pack_hl(v.y); p.z = pack_hl(v.z); p.w = pack_hl(v.w);
    *(uint4*)(g_hs_pk + (size_t)i * 4) = p;
}

// ---------------- router ----------------
__global__ void router_kernel(const float* __restrict__ hs,
                              const float* __restrict__ gw) {
    int warp = (blockIdx.x * blockDim.x + threadIdx.x) >> 5;
    int lane = threadIdx.x & 31;
    if (warp >= T) return;

    const float4* x4 = (const float4*)(hs + (size_t)warp * H);
    const float4* g4 = (const float4*)(gw + (size_t)lane * H);
    float acc = 0.f;
#pragma unroll 4
    for (int i = 0; i < H / 4; i++) {
        float4 xv = x4[i];
        float4 gv = g4[i];
        acc += xv.x * gv.x + xv.y * gv.y + xv.z * gv.z + xv.w * gv.w;
    }
    float m = acc;
#pragma unroll
    for (int o = 16; o; o >>= 1) m = fmaxf(m, __shfl_xor_sync(0xffffffffu, m, o));
    float p = __expf(acc - m);
    float s = p;
#pragma unroll
    for (int o = 16; o; o >>= 1) s += __shfl_xor_sync(0xffffffffu, s, o);
    float prob = p / s;

    float cur = prob;
    float wv[K];
    int   wid[K];
#pragma unroll
    for (int k = 0; k < K; k++) {
        float v = cur;
        int who = lane;
#pragma unroll
        for (int o = 16; o; o >>= 1) {
            float ov = __shfl_xor_sync(0xffffffffu, v, o);
            int   oi = __shfl_xor_sync(0xffffffffu, who, o);
            if (ov > v || (ov == v && oi < who)) { v = ov; who = oi; }
        }
        wv[k] = v;
        wid[k] = who;
        if (lane == who) cur = -1.f;
    }
    if (lane == 0) {
        float ws = wv[0] + wv[1] + wv[2] + wv[3];
        float inv = 1.f / ws;
#pragma unroll
        for (int k = 0; k < K; k++) {
            g_topk_w[warp * K + k]  = wv[k] * inv;
            g_topk_id[warp * K + k] = wid[k];
            atomicAdd(&g_count[wid[k]], 1);
        }
    }
}

__global__ void scan_kernel() {
    if (threadIdx.x == 0) {
        int acc = 0;
        for (int e = 0; e < E; e++) {
            g_offset[e] = acc;
            g_cursor[e] = acc;
            acc += g_count[e];
        }
        g_offset[E] = acc;
    }
}

__global__ void scatter_kernel() {
    int i = blockIdx.x * blockDim.x + threadIdx.x;
    if (i < T * K) {
        int e = g_topk_id[i];
        int pos = atomicAdd(&g_cursor[e], 1);
        g_assign_token[pos] = i >> 2;
        g_row_of[i] = pos;
    }
}

// ================= GEMM1 (HMMA bf16x3, pipelined) =================
// CTA: 128 rows x 64 f-cols. B rows interleaved: 2j = gate(fbase+j), 2j+1 = up(fbase+j).
__global__ __launch_bounds__(256) void gemm1_mma(const float* __restrict__ w1) {
    const int e  = blockIdx.y >> 3;
    const int mt = blockIdx.y & 7;
    const int rbeg = g_offset[e], rend = g_offset[e + 1];
    const int row0 = rbeg + mt * 128;
    if (row0 >= rend) return;
    const int fbase = blockIdx.x * 64;

    extern __shared__ __align__(16) char smem[];

    const int tid = threadIdx.x, lane = tid & 31;
    const int wm = (tid >> 5) & 3, wn = tid >> 7;

    // A-load roles: 128 rows x 8 uint4-slots of packed hs
    const uint32_t* aptr[4];
    uint32_t aoff[4];
#pragma unroll
    for (int i = 0; i < 4; i++) {
        int unit = tid + i * 256;
        int j = unit >> 3, s = unit & 7;
        int rr = row0 + j;
        int tok = g_assign_token[rr < rend ? rr : rbeg];
        aptr[i] = g_hs_pk + (size_t)tok * H + s * 4;
        aoff[i] = (uint32_t)(j * PITCH_B + s * 8);
    }
    // B-load roles: 128 interleaved B-rows x 8 quads of w1 fp32
    const float* bptr[4];
    uint32_t boff[4];
#pragma unroll
    for (int i = 0; i < 4; i++) {
        int unit = tid + i * 256;
        int n = unit >> 3, q = unit & 7;
        int j = n >> 1, s = n & 1;
        size_t grow = (size_t)e * (2 * F) + (s ? F : 0) + fbase + j;
        bptr[i] = w1 + grow * H + q * 4;
        boff[i] = (uint32_t)(n * PITCH_B + q * 8);
    }

    const uint32_t base = smem_u32(smem);

    float acc[16][4];
#pragma unroll
    for (int i = 0; i < 16; i++)
#pragma unroll
        for (int j = 0; j < 4; j++) acc[i][j] = 0.f;

    uint4  rA[4];
    float4 rB[4];
#pragma unroll
    for (int i = 0; i < 4; i++) { rA[i] = *(const uint4*)aptr[i]; rB[i] = *(const float4*)bptr[i]; }
    // stage chunk 0 into buf 0
#pragma unroll
    for (int i = 0; i < 4; i++) {
        uint2 hi, lo;
        unpack4(rA[i], hi, lo);
        *(uint2*)(smem + aoff[i]) = hi;
        *(uint2*)(smem + ASZ + aoff[i]) = lo;
        cvt_split4(rB[i], hi, lo);
        *(uint2*)(smem + 2 * ASZ + boff[i]) = hi;
        *(uint2*)(smem + 3 * ASZ + boff[i]) = lo;
    }
    __syncthreads();

    for (int c = 0; c < NC1; c++) {
        const uint32_t cb = base + (c & 1) * BUF_STRIDE;
        const uint32_t nb = base + ((c + 1) & 1) * BUF_STRIDE;
        char* nbp = smem + ((c + 1) & 1) * BUF_STRIDE;

        if (c + 1 < NC1) {
#pragma unroll
            for (int i = 0; i < 4; i++) {
                rA[i] = *(const uint4*)(aptr[i] + (c + 1) * KC);
                rB[i] = *(const float4*)(bptr[i] + (c + 1) * KC);
            }
        }

#pragma unroll
        for (int ks = 0; ks < 2; ks++) {
            const uint32_t kb = ks * 32;
            const uint32_t lrow = (lane & 15), lcol = (lane >> 4) * 16;
            uint32_t ah[2][4], al[2][4];
#pragma unroll
            for (int i = 0; i < 2; i++) {
                uint32_t off = (uint32_t)((wm * 32 + i * 16 + lrow) * PITCH_B) + lcol + kb;
                LDM4(ah[i], cb + off);
                LDM4(al[i], cb + ASZ + off);
            }
            uint32_t bh[4][4], bl[4][4];
#pragma unroll
            for (int j2 = 0; j2 < 4; j2++) {
                uint32_t off = (uint32_t)((wn * 64 + j2 * 16 + lrow) * PITCH_B) + lcol + kb;
                LDM4(bh[j2], cb + 2 * ASZ + off);
                LDM4(bl[j2], cb + 3 * ASZ + off);
            }
#pragma unroll
            for (int i = 0; i < 2; i++)
#pragma unroll
                for (int jt = 0; jt < 8; jt++) {
                    int j2 = jt >> 1, hsel = jt & 1;
                    float* d = acc[i * 8 + jt];
                    MMA16816(d, ah[i], bh[j2][hsel], bh[j2][2 + hsel]);
                    MMA16816(d, ah[i], bl[j2][hsel], bl[j2][2 + hsel]);
                    MMA16816(d, al[i], bh[j2][hsel], bh[j2][2 + hsel]);
                }
        }

        if (c + 1 < NC1) {
#pragma unroll
            for (int i = 0; i < 4; i++) {
                uint2 hi, lo;
                unpack4(rA[i], hi, lo);
                *(uint2*)(nbp + aoff[i]) = hi;
                *(uint2*)(nbp + ASZ + aoff[i]) = lo;
                cvt_split4(rB[i], hi, lo);
                *(uint2*)(nbp + 2 * ASZ + boff[i]) = hi;
                *(uint2*)(nbp + 3 * ASZ + boff[i]) = lo;
            }
        }
        __syncthreads();
    }

    // epilogue: (c0,c1)=(g,u) row r1; (c2,c3)=(g,u) row r1+8
#pragma unroll
    for (int i = 0; i < 2; i++)
#pragma unroll
        for (int jt = 0; jt < 8; jt++) {
            float* d = acc[i * 8 + jt];
            int f = fbase + wn * 32 + jt * 4 + (lane & 3);
            int r1 = row0 + wm * 32 + i * 16 + (lane >> 2);
            float a0 = silu(d[0]) * d[1];
            float a1 = silu(d[2]) * d[3];
            if (r1 < rend)     g_act_pk[(size_t)r1 * F + f] = pack_hl(a0);
            if (r1 + 8 < rend) g_act_pk[(size_t)(r1 + 8) * F + f] = pack_hl(a1);
        }
}

// ================= GEMM2 (HMMA bf16x3, pipelined): 128 rows x 128 h-cols =================
__global__ __launch_bounds__(256) void gemm2_mma(const float* __restrict__ w2) {
    const int e  = blockIdx.y >> 3;
    const int mt = blockIdx.y & 7;
    const int rbeg = g_offset[e], rend = g_offset[e + 1];
    const int row0 = rbeg + mt * 128;
    if (row0 >= rend) return;
    const int hbase = blockIdx.x * 128;

    extern __shared__ __align__(16) char smem[];

    const int tid = threadIdx.x, lane = tid & 31;
    const int wm = (tid >> 5) & 3, wn = tid >> 7;

    const uint32_t* aptr[4];
    uint32_t aoff[4];
#pragma unroll
    for (int i = 0; i < 4; i++) {
        int unit = tid + i * 256;
        int j = unit >> 3, s = unit & 7;
        int rr = row0 + j;
        int row = rr < rend ? rr : rbeg;
        aptr[i] = g_act_pk + (size_t)row * F + s * 4;
        aoff[i] = (uint32_t)(j * PITCH_B + s * 8);
    }
    const float* bptr[4];
    uint32_t boff[4];
#pragma unroll
    for (int i = 0; i < 4; i++) {
        int unit = tid + i * 256;
        int n = unit >> 3, q = unit & 7;
        bptr[i] = w2 + ((size_t)e * H + hbase + n) * F + q * 4;
        boff[i] = (uint32_t)(n * PITCH_B + q * 8);
    }

    const uint32_t base = smem_u32(smem);

    float acc[16][4];
#pragma unroll
    for (int i = 0; i < 16; i++)
#pragma unroll
        for (int j = 0; j < 4; j++) acc[i][j] = 0.f;

    uint4  rA[4];
    float4 rB[4];
#pragma unroll
    for (int i = 0; i < 4; i++) { rA[i] = *(const uint4*)aptr[i]; rB[i] = *(const float4*)bptr[i]; }
#pragma unroll
    for (int i = 0; i < 4; i++) {
        uint2 hi, lo;
        unpack4(rA[i], hi, lo);
        *(uint2*)(smem + aoff[i]) = hi;
        *(uint2*)(smem + ASZ + aoff[i]) = lo;
        cvt_split4(rB[i], hi, lo);
        *(uint2*)(smem + 2 * ASZ + boff[i]) = hi;
        *(uint2*)(smem + 3 * ASZ + boff[i]) = lo;
    }
    __syncthreads();

    for (int c = 0; c < NC2; c++) {
        const uint32_t cb = base + (c & 1) * BUF_STRIDE;
        char* nbp = smem + ((c + 1) & 1) * BUF_STRIDE;

        if (c + 1 < NC2) {
#pragma unroll
            for (int i = 0; i < 4; i++) {
                rA[i] = *(const uint4*)(aptr[i] + (c + 1) * KC);
                rB[i] = *(const float4*)(bptr[i] + (c + 1) * KC);
            }
        }

#pragma unroll
        for (int ks = 0; ks < 2; ks++) {
            const uint32_t kb = ks * 32;
            const uint32_t lrow = (lane & 15), lcol = (lane >> 4) * 16;
            uint32_t ah[2][4], al[2][4];
#pragma unroll
            for (int i = 0; i < 2; i++) {
                uint32_t off = (uint32_t)((wm * 32 + i * 16 + lrow) * PITCH_B) + lcol + kb;
                LDM4(ah[i], cb + off);
                LDM4(al[i], cb + ASZ + off);
            }
            uint32_t bh[4][4], bl[4][4];
#pragma unroll
            for (int j2 = 0; j2 < 4; j2++) {
                uint32_t off = (uint32_t)((wn * 64 + j2 * 16 + lrow) * PITCH_B) + lcol + kb;
                LDM4(bh[j2], cb + 2 * ASZ + off);
                LDM4(bl[j2], cb + 3 * ASZ + off);
            }
#pragma unroll
            for (int i = 0; i < 2; i++)
#pragma unroll
                for (int jt = 0; jt < 8; jt++) {
                    int j2 = jt >> 1, hsel = jt & 1;
                    float* d = acc[i * 8 + jt];
                    MMA16816(d, ah[i], bh[j2][hsel], bh[j2][2 + hsel]);
                    MMA16816(d, ah[i], bl[j2][hsel], bl[j2][2 + hsel]);
                    MMA16816(d, al[i], bh[j2][hsel], bh[j2][2 + hsel]);
                }
        }

        if (c + 1 < NC2) {
#pragma unroll
            for (int i = 0; i < 4; i++) {
                uint2 hi, lo;
                unpack4(rA[i], hi, lo);
                *(uint2*)(nbp + aoff[i]) = hi;
                *(uint2*)(nbp + ASZ + aoff[i]) = lo;
                cvt_split4(rB[i], hi, lo);
                *(uint2*)(nbp + 2 * ASZ + boff[i]) = hi;
                *(uint2*)(nbp + 3 * ASZ + boff[i]) = lo;
            }
        }
        __syncthreads();
    }

#pragma unroll
    for (int i = 0; i < 2; i++)
#pragma unroll
        for (int jt = 0; jt < 8; jt++) {
            float* d = acc[i * 8 + jt];
            int hcol = hbase + wn * 64 + jt * 8 + 2 * (lane & 3);
            int r1 = row0 + wm * 32 + i * 16 + (lane >> 2);
            if (r1 < rend)
                *(float2*)(g_y + (size_t)r1 * H + hcol) = make_float2(d[0], d[1]);
            if (r1 + 8 < rend)
                *(float2*)(g_y + (size_t)(r1 + 8) * H + hcol) = make_float2(d[2], d[3]);
        }
}

// ---------------- gather ----------------
__global__ void gather_kernel(float* __restrict__ out) {
    int t = blockIdx.x;
    __shared__ float ws[K];
    __shared__ int   rs[K];
    if (threadIdx.x < K) {
        ws[threadIdx.x] = g_topk_w[t * K + threadIdx.x];
        rs[threadIdx.x] = g_row_of[t * K + threadIdx.x];
    }
    __syncthreads();
    int h = threadIdx.x * 4;
    float4 acc = make_float4(0.f, 0.f, 0.f, 0.f);
#pragma unroll
    for (int k = 0; k < K; k++) {
        float4 v = *(const float4*)(g_y + (size_t)rs[k] * H + h);
        float w = ws[k];
        acc.x += w * v.x;
        acc.y += w * v.y;
        acc.z += w * v.z;
        acc.w += w * v.w;
    }
    *(float4*)(out + (size_t)t * H + h) = acc;
}

extern "C" void kernel_launch(void* const* d_in, const int* in_sizes, int n_in,
                              void* d_out, int out_size) {
    const float* hs = (const float*)d_in[0];
    const float* gw = (const float*)d_in[1];
    const float* w1 = (const float*)d_in[2];
    const float* w2 = (const float*)d_in[3];
    float* out = (float*)d_out;

    static bool attr_done = false;
    if (!attr_done) {
        cudaFuncSetAttribute(gemm1_mma, cudaFuncAttributeMaxDynamicSharedMemorySize, SMEM_TOTAL);
        cudaFuncSetAttribute(gemm2_mma, cudaFuncAttributeMaxDynamicSharedMemorySize, SMEM_TOTAL);
        attr_done = true;
    }

    init_kernel<<<1, 32>>>();
    hs_convert_kernel<<<T * H / 4 / 256, 256>>>(hs);
    router_kernel<<<T / 4, 128>>>(hs, gw);
    scan_kernel<<<1, 32>>>();
    scatter_kernel<<<(T * K + 255) / 256, 256>>>();
    gemm1_mma<<<dim3(F / 64, E * 8), 256, SMEM_TOTAL>>>(w1);
    gemm2_mma<<<dim3(H / 128, E * 8), 256, SMEM_TOTAL>>>(w2);
    gather_kernel<<<T, 256>>>(out);
}

// round 5
// speedup vs baseline: 1.0124x; 1.0124x over previous
#include <cuda_runtime.h>
#include <cuda_bf16.h>
#include <cstdint>

#define T 1024
#define H 1024
#define F 768
#define E 32
#define K 4

#define KC 32            // k elems per chunk
#define PITCH_B 80       // bytes per smem row -> conflict-free ldmatrix
#define ASZ (128 * PITCH_B)
#define BUF_STRIDE (4 * ASZ)
#define SMEM_TOTAL (2 * BUF_STRIDE)   /* 81920 */
#define NC1 (H / KC)     // 32
#define NC2 (F / KC)     // 24

// ---------------- scratch ----------------
__device__ float    g_topk_w[T * K];
__device__ int      g_topk_id[T * K];
__device__ int      g_offset[E + 1];
__device__ int      g_assign_token[T * K];
__device__ int      g_row_of[T * K];
__device__ uint32_t g_hs_pk[(size_t)T * H];       // packed bf16 hi|lo<<16
__device__ uint32_t g_act_pk[(size_t)T * K * F];  // packed bf16 hi|lo<<16
__device__ float    g_y[(size_t)T * K * H];

// ---------------- helpers ----------------
__device__ __forceinline__ uint32_t smem_u32(const void* p) {
    uint32_t a;
    asm("{ .reg .u64 t; cvta.to.shared.u64 t, %1; cvt.u32.u64 %0, t; }" : "=r"(a) : "l"(p));
    return a;
}

#define LDM4(r, addr) \
    asm volatile("ldmatrix.sync.aligned.m8n8.x4.shared.b16 {%0,%1,%2,%3}, [%4];" \
        : "=r"((r)[0]), "=r"((r)[1]), "=r"((r)[2]), "=r"((r)[3]) : "r"(addr))

#define MMA16816(d, a, b0, b1) \
    asm volatile("mma.sync.aligned.m16n8k16.row.col.f32.bf16.bf16.f32 " \
        "{%0,%1,%2,%3}, {%4,%5,%6,%7}, {%8,%9}, {%0,%1,%2,%3};" \
        : "+f"((d)[0]), "+f"((d)[1]), "+f"((d)[2]), "+f"((d)[3]) \
        : "r"((a)[0]), "r"((a)[1]), "r"((a)[2]), "r"((a)[3]), "r"(b0), "r"(b1))

// split float4 -> bf16 hi pair-packed + lo pair-packed
__device__ __forceinline__ void cvt_split4(float4 v, uint2& hi, uint2& lo) {
    uint32_t h01, h23, l01, l23;
    asm("cvt.rn.bf16x2.f32 %0, %1, %2;" : "=r"(h01) : "f"(v.y), "f"(v.x));
    asm("cvt.rn.bf16x2.f32 %0, %1, %2;" : "=r"(h23) : "f"(v.w), "f"(v.z));
    float h0 = __uint_as_float(h01 << 16), h1 = __uint_as_float(h01 & 0xFFFF0000u);
    float h2 = __uint_as_float(h23 << 16), h3 = __uint_as_float(h23 & 0xFFFF0000u);
    asm("cvt.rn.bf16x2.f32 %0, %1, %2;" : "=r"(l01) : "f"(v.y - h1), "f"(v.x - h0));
    asm("cvt.rn.bf16x2.f32 %0, %1, %2;" : "=r"(l23) : "f"(v.w - h3), "f"(v.z - h2));
    hi = make_uint2(h01, h23);
    lo = make_uint2(l01, l23);
}

__device__ __forceinline__ void unpack4(uint4 p, uint2& hi, uint2& lo) {
    hi.x = __byte_perm(p.x, p.y, 0x5410);
    hi.y = __byte_perm(p.z, p.w, 0x5410);
    lo.x = __byte_perm(p.x, p.y, 0x7632);
    lo.y = __byte_perm(p.z, p.w, 0x7632);
}

__device__ __forceinline__ uint32_t pack_hl(float a) {
    __nv_bfloat16 h = __float2bfloat16(a);
    float hf = __bfloat162float(h);
    __nv_bfloat16 l = __float2bfloat16(a - hf);
    return (uint32_t)__bfloat16_as_ushort(h) | ((uint32_t)__bfloat16_as_ushort(l) << 16);
}

__device__ __forceinline__ float silu(float x) { return x / (1.f + __expf(-x)); }

// ---------------- hs preconvert ----------------
__global__ void hs_convert_kernel(const float* __restrict__ hs) {
    int i = blockIdx.x * blockDim.x + threadIdx.x;
    float4 v = *(const float4*)(hs + (size_t)i * 4);
    uint4 p;
    p.x = pack_hl(v.x); p.y = pack_hl(v.y); p.z = pack_hl(v.z); p.w = pack_hl(v.w);
    *(uint4*)(g_hs_pk + (size_t)i * 4) = p;
}

// ---------------- router (no global atomics) ----------------
__global__ void router_kernel(const float* __restrict__ hs,
                              const float* __restrict__ gw) {
    int warp = (blockIdx.x * blockDim.x + threadIdx.x) >> 5;
    int lane = threadIdx.x & 31;
    if (warp >= T) return;

    const float4* x4 = (const float4*)(hs + (size_t)warp * H);
    const float4* g4 = (const float4*)(gw + (size_t)lane * H);
    float acc = 0.f;
#pragma unroll 4
    for (int i = 0; i < H / 4; i++) {
        float4 xv = x4[i];
        float4 gv = g4[i];
        acc += xv.x * gv.x + xv.y * gv.y + xv.z * gv.z + xv.w * gv.w;
    }
    float m = acc;
#pragma unroll
    for (int o = 16; o; o >>= 1) m = fmaxf(m, __shfl_xor_sync(0xffffffffu, m, o));
    float p = __expf(acc - m);
    float s = p;
#pragma unroll
    for (int o = 16; o; o >>= 1) s += __shfl_xor_sync(0xffffffffu, s, o);
    float prob = p / s;

    float cur = prob;
    float wv[K];
    int   wid[K];
#pragma unroll
    for (int k = 0; k < K; k++) {
        float v = cur;
        int who = lane;
#pragma unroll
        for (int o = 16; o; o >>= 1) {
            float ov = __shfl_xor_sync(0xffffffffu, v, o);
            int   oi = __shfl_xor_sync(0xffffffffu, who, o);
            if (ov > v || (ov == v && oi < who)) { v = ov; who = oi; }
        }
        wv[k] = v;
        wid[k] = who;
        if (lane == who) cur = -1.f;
    }
    if (lane == 0) {
        float ws = wv[0] + wv[1] + wv[2] + wv[3];
        float inv = 1.f / ws;
#pragma unroll
        for (int k = 0; k < K; k++) {
            g_topk_w[warp * K + k]  = wv[k] * inv;
            g_topk_id[warp * K + k] = wid[k];
        }
    }
}

// ---------------- bucket: count + scan + scatter in one block ----------------
__global__ void bucket_kernel() {
    __shared__ int cnt[E];
    __shared__ int curp[E];
    __shared__ int offp[E + 1];
    int t = threadIdx.x;   // one token per thread, 1024 threads
    if (t < E) cnt[t] = 0;
    __syncthreads();
    int ids[K];
#pragma unroll
    for (int k = 0; k < K; k++) {
        ids[k] = g_topk_id[t * K + k];
        atomicAdd(&cnt[ids[k]], 1);
    }
    __syncthreads();
    if (t == 0) {
        int a = 0;
        for (int e = 0; e < E; e++) { offp[e] = a; curp[e] = a; a += cnt[e]; }
        offp[E] = a;
    }
    __syncthreads();
#pragma unroll
    for (int k = 0; k < K; k++) {
        int pos = atomicAdd(&curp[ids[k]], 1);
        g_assign_token[pos] = t;
        g_row_of[t * K + k] = pos;
    }
    if (t <= E) g_offset[t] = offp[t];
}

// ================= GEMM1 (HMMA bf16x3, pass-major ILP) =================
__global__ __launch_bounds__(256) void gemm1_mma(const float* __restrict__ w1) {
    const int e  = blockIdx.y >> 3;
    const int mt = blockIdx.y & 7;
    const int rbeg = g_offset[e], rend = g_offset[e + 1];
    const int row0 = rbeg + mt * 128;
    if (row0 >= rend) return;
    const int fbase = blockIdx.x * 64;

    extern __shared__ __align__(16) char smem[];

    const int tid = threadIdx.x, lane = tid & 31;
    const int wm = (tid >> 5) & 3, wn = tid >> 7;

    const uint32_t* aptr[4];
    uint32_t aoff[4];
#pragma unroll
    for (int i = 0; i < 4; i++) {
        int unit = tid + i * 256;
        int j = unit >> 3, s = unit & 7;
        int rr = row0 + j;
        int tok = g_assign_token[rr < rend ? rr : rbeg];
        aptr[i] = g_hs_pk + (size_t)tok * H + s * 4;
        aoff[i] = (uint32_t)(j * PITCH_B + s * 8);
    }
    const float* bptr[4];
    uint32_t boff[4];
#pragma unroll
    for (int i = 0; i < 4; i++) {
        int unit = tid + i * 256;
        int n = unit >> 3, q = unit & 7;
        int j = n >> 1, s = n & 1;
        size_t grow = (size_t)e * (2 * F) + (s ? F : 0) + fbase + j;
        bptr[i] = w1 + grow * H + q * 4;
        boff[i] = (uint32_t)(n * PITCH_B + q * 8);
    }

    const uint32_t base = smem_u32(smem);

    float acc[16][4];
#pragma unroll
    for (int i = 0; i < 16; i++)
#pragma unroll
        for (int j = 0; j < 4; j++) acc[i][j] = 0.f;

    uint4  rA[4];
    float4 rB[4];
#pragma unroll
    for (int i = 0; i < 4; i++) { rA[i] = *(const uint4*)aptr[i]; rB[i] = *(const float4*)bptr[i]; }
#pragma unroll
    for (int i = 0; i < 4; i++) {
        uint2 hi, lo;
        unpack4(rA[i], hi, lo);
        *(uint2*)(smem + aoff[i]) = hi;
        *(uint2*)(smem + ASZ + aoff[i]) = lo;
        cvt_split4(rB[i], hi, lo);
        *(uint2*)(smem + 2 * ASZ + boff[i]) = hi;
        *(uint2*)(smem + 3 * ASZ + boff[i]) = lo;
    }
    __syncthreads();

    for (int c = 0; c < NC1; c++) {
        const uint32_t cb = base + (c & 1) * BUF_STRIDE;
        char* nbp = smem + ((c + 1) & 1) * BUF_STRIDE;

        if (c + 1 < NC1) {
#pragma unroll
            for (int i = 0; i < 4; i++) {
                rA[i] = *(const uint4*)(aptr[i] + (c + 1) * KC);
                rB[i] = *(const float4*)(bptr[i] + (c + 1) * KC);
            }
        }

#pragma unroll
        for (int ks = 0; ks < 2; ks++) {
            const uint32_t kb = ks * 32;
            const uint32_t lrow = (lane & 15), lcol = (lane >> 4) * 16;
            uint32_t ah[2][4], al[2][4];
#pragma unroll
            for (int i = 0; i < 2; i++) {
                uint32_t off = (uint32_t)((wm * 32 + i * 16 + lrow) * PITCH_B) + lcol + kb;
                LDM4(ah[i], cb + off);
                LDM4(al[i], cb + ASZ + off);
            }
            uint32_t bh[4][4], bl[4][4];
#pragma unroll
            for (int j2 = 0; j2 < 4; j2++) {
                uint32_t off = (uint32_t)((wn * 64 + j2 * 16 + lrow) * PITCH_B) + lcol + kb;
                LDM4(bh[j2], cb + 2 * ASZ + off);
                LDM4(bl[j2], cb + 3 * ASZ + off);
            }
            // pass-major: 16 independent MMAs per pass -> no acc dependency stalls
#pragma unroll
            for (int i = 0; i < 2; i++)
#pragma unroll
                for (int jt = 0; jt < 8; jt++) {
                    int j2 = jt >> 1, hsel = jt & 1;
                    MMA16816(acc[i * 8 + jt], ah[i], bh[j2][hsel], bh[j2][2 + hsel]);
                }
#pragma unroll
            for (int i = 0; i < 2; i++)
#pragma unroll
                for (int jt = 0; jt < 8; jt++) {
                    int j2 = jt >> 1, hsel = jt & 1;
                    MMA16816(acc[i * 8 + jt], ah[i], bl[j2][hsel], bl[j2][2 + hsel]);
                }
#pragma unroll
            for (int i = 0; i < 2; i++)
#pragma unroll
                for (int jt = 0; jt < 8; jt++) {
                    int j2 = jt >> 1, hsel = jt & 1;
                    MMA16816(acc[i * 8 + jt], al[i], bh[j2][hsel], bh[j2][2 + hsel]);
                }
        }

        if (c + 1 < NC1) {
#pragma unroll
            for (int i = 0; i < 4; i++) {
                uint2 hi, lo;
                unpack4(rA[i], hi, lo);
                *(uint2*)(nbp + aoff[i]) = hi;
                *(uint2*)(nbp + ASZ + aoff[i]) = lo;
                cvt_split4(rB[i], hi, lo);
                *(uint2*)(nbp + 2 * ASZ + boff[i]) = hi;
                *(uint2*)(nbp + 3 * ASZ + boff[i]) = lo;
            }
        }
        __syncthreads();
    }

#pragma unroll
    for (int i = 0; i < 2; i++)
#pragma unroll
        for (int jt = 0; jt < 8; jt++) {
            float* d = acc[i * 8 + jt];
            int f = fbase + wn * 32 + jt * 4 + (lane & 3);
            int r1 = row0 + wm * 32 + i * 16 + (lane >> 2);
            float a0 = silu(d[0]) * d[1];
            float a1 = silu(d[2]) * d[3];
            if (r1 < rend)     g_act_pk[(size_t)r1 * F + f] = pack_hl(a0);
            if (r1 + 8 < rend) g_act_pk[(size_t)(r1 + 8) * F + f] = pack_hl(a1);
        }
}

// ================= GEMM2 (HMMA bf16x3, pass-major ILP) =================
__global__ __launch_bounds__(256) void gemm2_mma(const float* __restrict__ w2) {
    const int e  = blockIdx.y >> 3;
    const int mt = blockIdx.y & 7;
    const int rbeg = g_offset[e], rend = g_offset[e + 1];
    const int row0 = rbeg + mt * 128;
    if (row0 >= rend) return;
    const int hbase = blockIdx.x * 128;

    extern __shared__ __align__(16) char smem[];

    const int tid = threadIdx.x, lane = tid & 31;
    const int wm = (tid >> 5) & 3, wn = tid >> 7;

    const uint32_t* aptr[4];
    uint32_t aoff[4];
#pragma unroll
    for (int i = 0; i < 4; i++) {
        int unit = tid + i * 256;
        int j = unit >> 3, s = unit & 7;
        int rr = row0 + j;
        int row = rr < rend ? rr : rbeg;
        aptr[i] = g_act_pk + (size_t)row * F + s * 4;
        aoff[i] = (uint32_t)(j * PITCH_B + s * 8);
    }
    const float* bptr[4];
    uint32_t boff[4];
#pragma unroll
    for (int i = 0; i < 4; i++) {
        int unit = tid + i * 256;
        int n = unit >> 3, q = unit & 7;
        bptr[i] = w2 + ((size_t)e * H + hbase + n) * F + q * 4;
        boff[i] = (uint32_t)(n * PITCH_B + q * 8);
    }

    const uint32_t base = smem_u32(smem);

    float acc[16][4];
#pragma unroll
    for (int i = 0; i < 16; i++)
#pragma unroll
        for (int j = 0; j < 4; j++) acc[i][j] = 0.f;

    uint4  rA[4];
    float4 rB[4];
#pragma unroll
    for (int i = 0; i < 4; i++) { rA[i] = *(const uint4*)aptr[i]; rB[i] = *(const float4*)bptr[i]; }
#pragma unroll
    for (int i = 0; i < 4; i++) {
        uint2 hi, lo;
        unpack4(rA[i], hi, lo);
        *(uint2*)(smem + aoff[i]) = hi;
        *(uint2*)(smem + ASZ + aoff[i]) = lo;
        cvt_split4(rB[i], hi, lo);
        *(uint2*)(smem + 2 * ASZ + boff[i]) = hi;
        *(uint2*)(smem + 3 * ASZ + boff[i]) = lo;
    }
    __syncthreads();

    for (int c = 0; c < NC2; c++) {
        const uint32_t cb = base + (c & 1) * BUF_STRIDE;
        char* nbp = smem + ((c + 1) & 1) * BUF_STRIDE;

        if (c + 1 < NC2) {
#pragma unroll
            for (int i = 0; i < 4; i++) {
                rA[i] = *(const uint4*)(aptr[i] + (c + 1) * KC);
                rB[i] = *(const float4*)(bptr[i] + (c + 1) * KC);
            }
        }

#pragma unroll
        for (int ks = 0; ks < 2; ks++) {
            const uint32_t kb = ks * 32;
            const uint32_t lrow = (lane & 15), lcol = (lane >> 4) * 16;
            uint32_t ah[2][4], al[2][4];
#pragma unroll
            for (int i = 0; i < 2; i++) {
                uint32_t off = (uint32_t)((wm * 32 + i * 16 + lrow) * PITCH_B) + lcol + kb;
                LDM4(ah[i], cb + off);
                LDM4(al[i], cb + ASZ + off);
            }
            uint32_t bh[4][4], bl[4][4];
#pragma unroll
            for (int j2 = 0; j2 < 4; j2++) {
                uint32_t off = (uint32_t)((wn * 64 + j2 * 16 + lrow) * PITCH_B) + lcol + kb;
                LDM4(bh[j2], cb + 2 * ASZ + off);
                LDM4(bl[j2], cb + 3 * ASZ + off);
            }
#pragma unroll
            for (int i = 0; i < 2; i++)
#pragma unroll
                for (int jt = 0; jt < 8; jt++) {
                    int j2 = jt >> 1, hsel = jt & 1;
                    MMA16816(acc[i * 8 + jt], ah[i], bh[j2][hsel], bh[j2][2 + hsel]);
                }
#pragma unroll
            for (int i = 0; i < 2; i++)
#pragma unroll
                for (int jt = 0; jt < 8; jt++) {
                    int j2 = jt >> 1, hsel = jt & 1;
                    MMA16816(acc[i * 8 + jt], ah[i], bl[j2][hsel], bl[j2][2 + hsel]);
                }
#pragma unroll
            for (int i = 0; i < 2; i++)
#pragma unroll
                for (int jt = 0; jt < 8; jt++) {
                    int j2 = jt >> 1, hsel = jt & 1;
                    MMA16816(acc[i * 8 + jt], al[i], bh[j2][hsel], bh[j2][2 + hsel]);
                }
        }

        if (c + 1 < NC2) {
#pragma unroll
            for (int i = 0; i < 4; i++) {
                uint2 hi, lo;
                unpack4(rA[i], hi, lo);
                *(uint2*)(nbp + aoff[i]) = hi;
                *(uint2*)(nbp + ASZ + aoff[i]) = lo;
                cvt_split4(rB[i], hi, lo);
                *(uint2*)(nbp + 2 * ASZ + boff[i]) = hi;
                *(uint2*)(nbp + 3 * ASZ + boff[i]) = lo;
            }
        }
        __syncthreads();
    }

#pragma unroll
    for (int i = 0; i < 2; i++)
#pragma unroll
        for (int jt = 0; jt < 8; jt++) {
            float* d = acc[i * 8 + jt];
            int hcol = hbase + wn * 64 + jt * 8 + 2 * (lane & 3);
            int r1 = row0 + wm * 32 + i * 16 + (lane >> 2);
            if (r1 < rend)
                *(float2*)(g_y + (size_t)r1 * H + hcol) = make_float2(d[0], d[1]);
            if (r1 + 8 < rend)
                *(float2*)(g_y + (size_t)(r1 + 8) * H + hcol) = make_float2(d[2], d[3]);
        }
}

// ---------------- gather ----------------
__global__ void gather_kernel(float* __restrict__ out) {
    int t = blockIdx.x;
    __shared__ float ws[K];
    __shared__ int   rs[K];
    if (threadIdx.x < K) {
        ws[threadIdx.x] = g_topk_w[t * K + threadIdx.x];
        rs[threadIdx.x] = g_row_of[t * K + threadIdx.x];
    }
    __syncthreads();
    int h = threadIdx.x * 4;
    float4 acc = make_float4(0.f, 0.f, 0.f, 0.f);
#pragma unroll
    for (int k = 0; k < K; k++) {
        float4 v = *(const float4*)(g_y + (size_t)rs[k] * H + h);
        float w = ws[k];
        acc.x += w * v.x;
        acc.y += w * v.y;
        acc.z += w * v.z;
        acc.w += w * v.w;
    }
    *(float4*)(out + (size_t)t * H + h) = acc;
}

extern "C" void kernel_launch(void* const* d_in, const int* in_sizes, int n_in,
                              void* d_out, int out_size) {
    const float* hs = (const float*)d_in[0];
    const float* gw = (const float*)d_in[1];
    const float* w1 = (const float*)d_in[2];
    const float* w2 = (const float*)d_in[3];
    float* out = (float*)d_out;

    static bool attr_done = false;
    if (!attr_done) {
        cudaFuncSetAttribute(gemm1_mma, cudaFuncAttributeMaxDynamicSharedMemorySize, SMEM_TOTAL);
        cudaFuncSetAttribute(gemm2_mma, cudaFuncAttributeMaxDynamicSharedMemorySize, SMEM_TOTAL);
        attr_done = true;
    }

    hs_convert_kernel<<<T * H / 4 / 256, 256>>>(hs);
    router_kernel<<<T / 4, 128>>>(hs, gw);
    bucket_kernel<<<1, 1024>>>();
    gemm1_mma<<<dim3(F / 64, E * 8), 256, SMEM_TOTAL>>>(w1);
    gemm2_mma<<<dim3(H / 128, E * 8), 256, SMEM_TOTAL>>>(w2);
    gather_kernel<<<T, 256>>>(out);
}